// round 7
// baseline (speedup 1.0000x reference)
#include <cuda_runtime.h>
#include <math.h>

#define NB 8
#define IMGW 120
#define TGRID 1024
#define PPTS 1024

#define C1_THREADS (NB * 4 * 57 * 57)            // 103968 (2 oc per thread)
#define C1_BLOCKS ((C1_THREADS + 255) / 256)     // 407
#define C2_THREADS (NB * 10 * 26 * 26)
#define C2_BLOCKS ((C2_THREADS + 255) / 256)     // 212

#define H1_STRIDE 58
#define PL4 (TGRID * TGRID / 4)                  // 262144 float4 per plane (2^18)

__device__ float g_h1[NB * 8 * 57 * H1_STRIDE];
__device__ float g_h2[NB * 10 * 26 * 26];
__device__ unsigned g_bar_count;
__device__ unsigned g_bar_gen;

__device__ __forceinline__ void grid_barrier() {
    __syncthreads();
    if (threadIdx.x == 0) {
        unsigned gen = *((volatile unsigned*)&g_bar_gen);
        __threadfence();
        if (atomicAdd(&g_bar_count, 1u) == gridDim.x - 1) {
            g_bar_count = 0;
            __threadfence();
            atomicAdd(&g_bar_gen, 1u);
        } else {
            while (*((volatile unsigned*)&g_bar_gen) == gen) { __nanosleep(64); }
        }
        __threadfence();
    }
    __syncthreads();
}

// fill planes [plane0, plane0+nplanes) using `nblk` blocks; lb = local block idx
__device__ __forceinline__ void fill_range(float4* __restrict__ ofill,
                                           const float* __restrict__ s_cst,
                                           int plane0, int nplanes,
                                           int lb, int nblk) {
    const long total = (long)nplanes * PL4;
    const long stride = (long)nblk * 256;
    const size_t base = (size_t)plane0 * PL4;
    for (long i = (long)lb * 256 + threadIdx.x; i < total; i += stride) {
        float c = s_cst[plane0 + (int)(i >> 18)];
        ofill[base + i] = make_float4(c, c, c, c);
    }
}

__global__ __launch_bounds__(256, 4) void fused_kernel(
    const float* __restrict__ x,   const float* __restrict__ uv,
    const float* __restrict__ xyz, const float* __restrict__ w1,
    const float* __restrict__ b1,  const float* __restrict__ w2,
    const float* __restrict__ b2,  const float* __restrict__ fw1,
    const float* __restrict__ fb1, const float* __restrict__ fw2,
    const float* __restrict__ fb2, float* __restrict__ out) {

    __shared__ float s_cst[24];
    __shared__ float sh[2016];
    __shared__ float sbias[10];
    __shared__ float s_small[52];

    const int bid = blockIdx.x;
    const int tid = threadIdx.x;
    const int nblk = gridDim.x;
    float4* ofill = reinterpret_cast<float4*>(out + 96);

    if (tid < 24) {
        const float* xb = x + (size_t)tid * IMGW * IMGW;
        s_cst[tid] = 0.25f * (__ldg(xb + 59 * IMGW + 59) + __ldg(xb + 59 * IMGW + 60) +
                              __ldg(xb + 60 * IMGW + 59) + __ldg(xb + 60 * IMGW + 60));
    }

    // ============ phase 1: conv1 (blocks <407) || fill planes 0-8 (blocks >=407) ====
    if (bid < C1_BLOCKS) {
        for (int i = tid; i < 8 * 3 * 49; i += 256) sh[i] = w1[i];
        if (tid < 8) sbias[tid] = b1[tid];
        __syncthreads();

        int idx = bid * 256 + tid;
        if (idx < C1_THREADS) {
            int px  = idx % 57;
            int py  = (idx / 57) % 57;
            int ocg = (idx / 3249) & 3;
            int n   = idx / 12996;

            float acc[2][4];
#pragma unroll
            for (int oc = 0; oc < 2; oc++)
                acc[oc][0] = acc[oc][1] = acc[oc][2] = acc[oc][3] = 0.f;

            const float* xb = x + (size_t)n * 3 * IMGW * IMGW;
            for (int ic = 0; ic < 3; ic++) {
                const float* xc = xb + ic * IMGW * IMGW + (2 * py) * IMGW + 2 * px;
#pragma unroll
                for (int wy = 0; wy < 8; wy++) {
                    const float2* row = reinterpret_cast<const float2*>(xc + wy * IMGW);
                    float v[8];
#pragma unroll
                    for (int j = 0; j < 4; j++) {
                        float2 t = __ldg(row + j);
                        v[2 * j] = t.x; v[2 * j + 1] = t.y;
                    }
#pragma unroll
                    for (int oc = 0; oc < 2; oc++) {
                        const float* wr = sh + ((ocg * 2 + oc) * 3 + ic) * 49;
                        if (wy < 7) {
#pragma unroll
                            for (int kx = 0; kx < 7; kx++) {
                                float wv = wr[wy * 7 + kx];
                                acc[oc][0] = fmaf(wv, v[kx], acc[oc][0]);
                                acc[oc][1] = fmaf(wv, v[kx + 1], acc[oc][1]);
                            }
                        }
                        if (wy >= 1) {
#pragma unroll
                            for (int kx = 0; kx < 7; kx++) {
                                float wv = wr[(wy - 1) * 7 + kx];
                                acc[oc][2] = fmaf(wv, v[kx], acc[oc][2]);
                                acc[oc][3] = fmaf(wv, v[kx + 1], acc[oc][3]);
                            }
                        }
                    }
                }
            }
#pragma unroll
            for (int oc = 0; oc < 2; oc++) {
                int woc = ocg * 2 + oc;
                float m = fmaxf(fmaxf(acc[oc][0], acc[oc][1]), fmaxf(acc[oc][2], acc[oc][3]));
                g_h1[((n * 8 + woc) * 57 + py) * H1_STRIDE + px] = fmaxf(m + sbias[woc], 0.f);
            }
        }
        // conv blocks then fill planes 9-13
        fill_range(ofill, s_cst, 9, 5, bid, C1_BLOCKS);
    } else {
        __syncthreads();   // s_cst visible
        fill_range(ofill, s_cst, 0, 9, bid - C1_BLOCKS, nblk - C1_BLOCKS);
    }
    grid_barrier();

    // ============ phase 2: conv2 (blocks <212) || fill planes 14-20 (blocks >=212) ==
    if (bid < C2_BLOCKS) {
        for (int i = tid; i < 2000; i += 256) sh[i] = w2[i];
        if (tid < 10) sbias[tid] = b2[tid];
        __syncthreads();

        int idx = bid * 256 + tid;
        if (idx < C2_THREADS) {
            int px = idx % 26;
            int py = (idx / 26) % 26;
            int oc = (idx / 676) % 10;
            int n  = idx / 6760;

            float a0 = 0.f, a1 = 0.f, a2 = 0.f, a3 = 0.f;
            for (int ic = 0; ic < 8; ic++) {
                const float* xc = g_h1 + ((n * 8 + ic) * 57 + 2 * py) * H1_STRIDE + 2 * px;
                const float* wr = sh + (oc * 8 + ic) * 25;
#pragma unroll
                for (int wy = 0; wy < 6; wy++) {
                    const float2* row = reinterpret_cast<const float2*>(xc + wy * H1_STRIDE);
                    float v[6];
#pragma unroll
                    for (int j = 0; j < 3; j++) {
                        float2 t = row[j];
                        v[2 * j] = t.x; v[2 * j + 1] = t.y;
                    }
                    if (wy < 5) {
#pragma unroll
                        for (int kx = 0; kx < 5; kx++) {
                            float wv = wr[wy * 5 + kx];
                            a0 = fmaf(wv, v[kx], a0);
                            a1 = fmaf(wv, v[kx + 1], a1);
                        }
                    }
                    if (wy >= 1) {
#pragma unroll
                        for (int kx = 0; kx < 5; kx++) {
                            float wv = wr[(wy - 1) * 5 + kx];
                            a2 = fmaf(wv, v[kx], a2);
                            a3 = fmaf(wv, v[kx + 1], a3);
                        }
                    }
                }
            }
            float m = fmaxf(fmaxf(a0, a1), fmaxf(a2, a3));
            g_h2[idx] = fmaxf(m + sbias[oc], 0.f);
        }
        // conv2 blocks then fill planes 21-23
        fill_range(ofill, s_cst, 21, 3, bid, C2_BLOCKS);
    } else {
        fill_range(ofill, s_cst, 14, 7, bid - C2_BLOCKS, nblk - C2_BLOCKS);
    }
    grid_barrier();

    // ============ phase 3: block n (0-7): fc1 + fc2 + Rodrigues + scatter ==========
    if (bid >= NB) return;
    {
        const int n = bid;
        const int w = tid >> 5;
        const int lane = tid & 31;
        float* z = s_small;            // 32
        float* theta = s_small + 32;   // 7
        float* Tm = s_small + 39;      // 12

        const float4* hrow = reinterpret_cast<const float4*>(g_h2 + n * 6760);
#pragma unroll
        for (int r = 0; r < 4; r++) {
            int j = (w << 2) | r;
            const float4* wrow = reinterpret_cast<const float4*>(fw1 + j * 6760);
            float s = 0.f;
#pragma unroll 4
            for (int k4 = lane; k4 < 1690; k4 += 32) {
                float4 wv = __ldg(wrow + k4);
                float4 hv = hrow[k4];
                s = fmaf(wv.x, hv.x, s);
                s = fmaf(wv.y, hv.y, s);
                s = fmaf(wv.z, hv.z, s);
                s = fmaf(wv.w, hv.w, s);
            }
#pragma unroll
            for (int off = 16; off; off >>= 1) s += __shfl_down_sync(0xffffffffu, s, off);
            if (lane == 0) z[j] = fmaxf(s + fb1[j], 0.f);
        }
        __syncthreads();

        if (tid < 7) {
            float a = fb2[tid];
#pragma unroll
            for (int jj = 0; jj < 32; jj++) a = fmaf(fw2[tid * 32 + jj], z[jj], a);
            theta[tid] = a;
        }
        __syncthreads();
        if (tid == 0) {
            float s0 = fabsf(theta[0]);
            float vx = theta[1], vy = theta[2], vz = theta[3];
            float ang = sqrtf(vx * vx + vy * vy + vz * vz + 1e-8f);
            float kx = vx / ang, ky = vy / ang, kz = vz / ang;
            float sn = sinf(ang);
            float cc = 1.0f - cosf(ang);
            float K[9] = {0.f, -kz, ky,  kz, 0.f, -kx,  -ky, kx, 0.f};
#pragma unroll
            for (int i = 0; i < 3; i++) {
#pragma unroll
                for (int jj = 0; jj < 3; jj++) {
                    float kk = 0.f;
#pragma unroll
                    for (int m = 0; m < 3; m++) kk += K[i * 3 + m] * K[m * 3 + jj];
                    Tm[i * 4 + jj] = (((i == jj) ? 1.f : 0.f) + sn * K[i * 3 + jj] + cc * kk) * s0;
                }
                Tm[i * 4 + 3] = theta[4 + i];
            }
        }
        __syncthreads();

        if (tid < 12) out[n * 12 + tid] = Tm[tid];

#pragma unroll
        for (int k = 0; k < 4; k++) {
            int p = k * 256 + tid;
            float X = xyz[p * 3 + 0], Y = xyz[p * 3 + 1], Z = xyz[p * 3 + 2];
            float p0 = Tm[0] * X + Tm[1] * Y + Tm[2] * Z + Tm[3];
            float p1 = Tm[4] * X + Tm[5] * Y + Tm[6] * Z + Tm[7];

            float xs = p0 / (float)IMGW * 2.0f - 1.0f;
            float ys = -(p1 / (float)IMGW * 2.0f - 1.0f);

            float ix = ((xs + 1.0f) * (float)IMGW - 1.0f) * 0.5f;
            float iy = ((ys + 1.0f) * (float)IMGW - 1.0f) * 0.5f;

            float ix0f = floorf(ix), iy0f = floorf(iy);
            float ix1f = ix0f + 1.0f, iy1f = iy0f + 1.0f;
            float wx1 = ix - ix0f, wx0 = 1.0f - wx1;
            float wy1 = iy - iy0f, wy0 = 1.0f - wy1;

            bool vx0 = (ix0f >= 0.f) && (ix0f < (float)IMGW);
            bool vx1 = (ix1f >= 0.f) && (ix1f < (float)IMGW);
            bool vy0 = (iy0f >= 0.f) && (iy0f < (float)IMGW);
            bool vy1 = (iy1f >= 0.f) && (iy1f < (float)IMGW);

            int ii0 = (int)fminf(fmaxf(ix0f, 0.f), (float)(IMGW - 1));
            int ii1 = (int)fminf(fmaxf(ix1f, 0.f), (float)(IMGW - 1));
            int jj0 = (int)fminf(fmaxf(iy0f, 0.f), (float)(IMGW - 1));
            int jj1 = (int)fminf(fmaxf(iy1f, 0.f), (float)(IMGW - 1));

            int pxg = (int)floorf(uv[p * 2 + 0] * (float)TGRID);
            int pyg = (int)floorf(uv[p * 2 + 1] * (float)TGRID);
            bool inb = (pxg >= 0) && (pxg < TGRID) && (pyg >= 0) && (pyg < TGRID);

            float w00 = wy0 * wx0, w01 = wy0 * wx1, w10 = wy1 * wx0, w11 = wy1 * wx1;

            if (inb) {
#pragma unroll
                for (int c = 0; c < 3; c++) {
                    const float* base = x + ((size_t)(n * 3 + c)) * IMGW * IMGW;
                    float v00 = (vy0 && vx0) ? __ldg(base + jj0 * IMGW + ii0) : 0.f;
                    float v01 = (vy0 && vx1) ? __ldg(base + jj0 * IMGW + ii1) : 0.f;
                    float v10 = (vy1 && vx0) ? __ldg(base + jj1 * IMGW + ii0) : 0.f;
                    float v11 = (vy1 && vx1) ? __ldg(base + jj1 * IMGW + ii1) : 0.f;
                    float val = v00 * w00 + v01 * w01 + v10 * w10 + v11 * w11;
                    out[96 + (((size_t)(n * 3 + c)) << 20) + (size_t)pxg * TGRID + pyg] = val;
                }
            }
        }
    }
}

extern "C" void kernel_launch(void* const* d_in, const int* in_sizes, int n_in,
                              void* d_out, int out_size) {
    const float* x   = (const float*)d_in[0];
    const float* uv  = (const float*)d_in[1];
    const float* xyz = (const float*)d_in[2];
    const float* w1  = (const float*)d_in[3];
    const float* b1  = (const float*)d_in[4];
    const float* w2  = (const float*)d_in[5];
    const float* b2  = (const float*)d_in[6];
    const float* fw1 = (const float*)d_in[7];
    const float* fb1 = (const float*)d_in[8];
    const float* fw2 = (const float*)d_in[9];
    const float* fb2 = (const float*)d_in[10];
    float* out = (float*)d_out;

    int dev = 0, sms = 148;
    cudaGetDevice(&dev);
    cudaDeviceGetAttribute(&sms, cudaDevAttrMultiProcessorCount, dev);
    int nblocks = 4 * sms;
    if (nblocks < C1_BLOCKS + 64) nblocks = C1_BLOCKS + 64;

    fused_kernel<<<nblocks, 256>>>(x, uv, xyz, w1, b1, w2, b2,
                                   fw1, fb1, fw2, fb2, out);
}

// round 8
// speedup vs baseline: 1.0576x; 1.0576x over previous
#include <cuda_runtime.h>
#include <math.h>

#define NB 8
#define IMGW 120
#define TGRID 1024
#define PPTS 1024

#define C1_THREADS (NB * 2 * 57 * 57)
#define C1_BLOCKS ((C1_THREADS + 255) / 256)     // 204
#define C2_THREADS (NB * 10 * 26 * 26)
#define C2_BLOCKS ((C2_THREADS + 255) / 256)     // 212

#define H1_STRIDE 58

// scratch (no allocations allowed)
__device__ float g_h1[NB * 8 * 57 * H1_STRIDE];
__device__ float g_h2[NB * 10 * 26 * 26];
__device__ float g_z[NB * 32];

// ---------------- conv1 (3->8, 7x7, pool, relu) ----------------
__global__ __launch_bounds__(256) void conv1_kernel(const float* __restrict__ x,
                                                    const float* __restrict__ w,
                                                    const float* __restrict__ b) {
    __shared__ float ws[8 * 3 * 49];
    __shared__ float bs[8];
    for (int i = threadIdx.x; i < 8 * 3 * 49; i += 256) ws[i] = w[i];
    if (threadIdx.x < 8) bs[threadIdx.x] = b[threadIdx.x];
    __syncthreads();

    int idx = blockIdx.x * 256 + threadIdx.x;
    if (idx >= C1_THREADS) return;
    int px  = idx % 57;
    int py  = (idx / 57) % 57;
    int ocg = (idx / 3249) & 1;
    int n   = idx / 6498;

    float acc[4][4];
#pragma unroll
    for (int oc = 0; oc < 4; oc++)
        acc[oc][0] = acc[oc][1] = acc[oc][2] = acc[oc][3] = 0.f;

    const float* xb = x + (size_t)n * 3 * IMGW * IMGW;
    for (int ic = 0; ic < 3; ic++) {
        const float* xc = xb + ic * IMGW * IMGW + (2 * py) * IMGW + 2 * px;
#pragma unroll
        for (int wy = 0; wy < 8; wy++) {
            const float2* row = reinterpret_cast<const float2*>(xc + wy * IMGW);
            float v[8];
#pragma unroll
            for (int j = 0; j < 4; j++) {
                float2 t = __ldg(row + j);
                v[2 * j] = t.x; v[2 * j + 1] = t.y;
            }
#pragma unroll
            for (int oc = 0; oc < 4; oc++) {
                const float* wr = ws + ((ocg * 4 + oc) * 3 + ic) * 49;
                if (wy < 7) {
#pragma unroll
                    for (int kx = 0; kx < 7; kx++) {
                        float wv = wr[wy * 7 + kx];
                        acc[oc][0] = fmaf(wv, v[kx], acc[oc][0]);
                        acc[oc][1] = fmaf(wv, v[kx + 1], acc[oc][1]);
                    }
                }
                if (wy >= 1) {
#pragma unroll
                    for (int kx = 0; kx < 7; kx++) {
                        float wv = wr[(wy - 1) * 7 + kx];
                        acc[oc][2] = fmaf(wv, v[kx], acc[oc][2]);
                        acc[oc][3] = fmaf(wv, v[kx + 1], acc[oc][3]);
                    }
                }
            }
        }
    }
#pragma unroll
    for (int oc = 0; oc < 4; oc++) {
        int woc = ocg * 4 + oc;
        float m = fmaxf(fmaxf(acc[oc][0], acc[oc][1]), fmaxf(acc[oc][2], acc[oc][3]));
        g_h1[((n * 8 + woc) * 57 + py) * H1_STRIDE + px] = fmaxf(m + bs[woc], 0.f);
    }
}

// ---------------- conv2 (8->10, 5x5, pool, relu) ----------------
__global__ __launch_bounds__(256) void conv2_kernel(const float* __restrict__ w,
                                                    const float* __restrict__ b) {
    __shared__ float ws[10 * 8 * 25];
    __shared__ float bs[10];
    for (int i = threadIdx.x; i < 2000; i += 256) ws[i] = w[i];
    if (threadIdx.x < 10) bs[threadIdx.x] = b[threadIdx.x];
    __syncthreads();

    int idx = blockIdx.x * 256 + threadIdx.x;
    if (idx >= C2_THREADS) return;
    int px = idx % 26;
    int py = (idx / 26) % 26;
    int oc = (idx / 676) % 10;
    int n  = idx / 6760;

    float a0 = 0.f, a1 = 0.f, a2 = 0.f, a3 = 0.f;
    for (int ic = 0; ic < 8; ic++) {
        const float* xc = g_h1 + ((n * 8 + ic) * 57 + 2 * py) * H1_STRIDE + 2 * px;
        const float* wr = ws + (oc * 8 + ic) * 25;
#pragma unroll
        for (int wy = 0; wy < 6; wy++) {
            const float2* row = reinterpret_cast<const float2*>(xc + wy * H1_STRIDE);
            float v[6];
#pragma unroll
            for (int j = 0; j < 3; j++) {
                float2 t = row[j];
                v[2 * j] = t.x; v[2 * j + 1] = t.y;
            }
            if (wy < 5) {
#pragma unroll
                for (int kx = 0; kx < 5; kx++) {
                    float wv = wr[wy * 5 + kx];
                    a0 = fmaf(wv, v[kx], a0);
                    a1 = fmaf(wv, v[kx + 1], a1);
                }
            }
            if (wy >= 1) {
#pragma unroll
                for (int kx = 0; kx < 5; kx++) {
                    float wv = wr[(wy - 1) * 5 + kx];
                    a2 = fmaf(wv, v[kx], a2);
                    a3 = fmaf(wv, v[kx + 1], a3);
                }
            }
        }
    }
    float m = fmaxf(fmaxf(a0, a1), fmaxf(a2, a3));
    g_h2[idx] = fmaxf(m + bs[oc], 0.f);
}

// ---------------- fc1: warp per (n,j), coalesced float4 ----------------
__global__ __launch_bounds__(256) void fc1_kernel(const float* __restrict__ fw1,
                                                  const float* __restrict__ fb1) {
    int wid = threadIdx.x >> 5;
    int lane = threadIdx.x & 31;
    int wg = blockIdx.x * 8 + wid;       // 0..255
    int n = wg >> 5;
    int j = wg & 31;

    const float4* wrow = reinterpret_cast<const float4*>(fw1 + j * 6760);
    const float4* hrow = reinterpret_cast<const float4*>(g_h2 + n * 6760);
    float s = 0.f;
#pragma unroll 4
    for (int k4 = lane; k4 < 1690; k4 += 32) {
        float4 wv = __ldg(wrow + k4);
        float4 hv = hrow[k4];
        s = fmaf(wv.x, hv.x, s);
        s = fmaf(wv.y, hv.y, s);
        s = fmaf(wv.z, hv.z, s);
        s = fmaf(wv.w, hv.w, s);
    }
#pragma unroll
    for (int off = 16; off; off >>= 1) s += __shfl_down_sync(0xffffffffu, s, off);
    if (lane == 0) g_z[n * 32 + j] = fmaxf(s + fb1[j], 0.f);
}

// ---------------- fill: background constants, 64 blocks x 24 planes ----------
__global__ __launch_bounds__(256) void fill_kernel(const float* __restrict__ x,
                                                   float* __restrict__ out96) {
    int plane = blockIdx.y;           // 0..23
    const float* xb = x + (size_t)plane * IMGW * IMGW;
    float cst = 0.25f * (__ldg(xb + 59 * IMGW + 59) + __ldg(xb + 59 * IMGW + 60) +
                         __ldg(xb + 60 * IMGW + 59) + __ldg(xb + 60 * IMGW + 60));
    float4 v = make_float4(cst, cst, cst, cst);
    float4* o = reinterpret_cast<float4*>(out96 + (size_t)plane * TGRID * TGRID);
    int stride = gridDim.x * 256;
#pragma unroll 4
    for (int i = blockIdx.x * 256 + threadIdx.x; i < (TGRID * TGRID / 4); i += stride)
        o[i] = v;
}

// ---------------- scatter: fc2 + Rodrigues + bilinear, 32 blocks -------------
__global__ __launch_bounds__(256) void scatter_kernel(const float* __restrict__ x,
                                                      const float* __restrict__ uv,
                                                      const float* __restrict__ xyz,
                                                      const float* __restrict__ fw2,
                                                      const float* __restrict__ fb2,
                                                      float* __restrict__ out) {
    int b = blockIdx.x;
    int n = b >> 2;
    int q = b & 3;
    int t = threadIdx.x;

    __shared__ float z[32];
    __shared__ float theta[7];
    __shared__ float Tm[12];

    if (t < 32) z[t] = g_z[n * 32 + t];
    __syncthreads();
    if (t < 7) {
        float a = fb2[t];
#pragma unroll
        for (int jj = 0; jj < 32; jj++) a = fmaf(fw2[t * 32 + jj], z[jj], a);
        theta[t] = a;
    }
    __syncthreads();
    if (t == 0) {
        float s0 = fabsf(theta[0]);
        float vx = theta[1], vy = theta[2], vz = theta[3];
        float ang = sqrtf(vx * vx + vy * vy + vz * vz + 1e-8f);
        float kx = vx / ang, ky = vy / ang, kz = vz / ang;
        float sn = sinf(ang);
        float cc = 1.0f - cosf(ang);
        float K[9] = {0.f, -kz, ky,  kz, 0.f, -kx,  -ky, kx, 0.f};
#pragma unroll
        for (int i = 0; i < 3; i++) {
#pragma unroll
            for (int jj = 0; jj < 3; jj++) {
                float kk = 0.f;
#pragma unroll
                for (int m = 0; m < 3; m++) kk += K[i * 3 + m] * K[m * 3 + jj];
                Tm[i * 4 + jj] = (((i == jj) ? 1.f : 0.f) + sn * K[i * 3 + jj] + cc * kk) * s0;
            }
            Tm[i * 4 + 3] = theta[4 + i];
        }
    }
    __syncthreads();

    if (q == 0 && t < 12) out[n * 12 + t] = Tm[t];

    int p = q * 256 + t;
    float X = xyz[p * 3 + 0], Y = xyz[p * 3 + 1], Z = xyz[p * 3 + 2];
    float p0 = Tm[0] * X + Tm[1] * Y + Tm[2] * Z + Tm[3];
    float p1 = Tm[4] * X + Tm[5] * Y + Tm[6] * Z + Tm[7];

    float xs = p0 / (float)IMGW * 2.0f - 1.0f;
    float ys = -(p1 / (float)IMGW * 2.0f - 1.0f);

    float ix = ((xs + 1.0f) * (float)IMGW - 1.0f) * 0.5f;
    float iy = ((ys + 1.0f) * (float)IMGW - 1.0f) * 0.5f;

    float ix0f = floorf(ix), iy0f = floorf(iy);
    float ix1f = ix0f + 1.0f, iy1f = iy0f + 1.0f;
    float wx1 = ix - ix0f, wx0 = 1.0f - wx1;
    float wy1 = iy - iy0f, wy0 = 1.0f - wy1;

    bool vx0 = (ix0f >= 0.f) && (ix0f < (float)IMGW);
    bool vx1 = (ix1f >= 0.f) && (ix1f < (float)IMGW);
    bool vy0 = (iy0f >= 0.f) && (iy0f < (float)IMGW);
    bool vy1 = (iy1f >= 0.f) && (iy1f < (float)IMGW);

    int ii0 = (int)fminf(fmaxf(ix0f, 0.f), (float)(IMGW - 1));
    int ii1 = (int)fminf(fmaxf(ix1f, 0.f), (float)(IMGW - 1));
    int jj0 = (int)fminf(fmaxf(iy0f, 0.f), (float)(IMGW - 1));
    int jj1 = (int)fminf(fmaxf(iy1f, 0.f), (float)(IMGW - 1));

    int pxg = (int)floorf(uv[p * 2 + 0] * (float)TGRID);
    int pyg = (int)floorf(uv[p * 2 + 1] * (float)TGRID);
    if (pxg < 0 || pxg >= TGRID || pyg < 0 || pyg >= TGRID) return;

    float w00 = wy0 * wx0, w01 = wy0 * wx1, w10 = wy1 * wx0, w11 = wy1 * wx1;

#pragma unroll
    for (int c = 0; c < 3; c++) {
        const float* base = x + ((size_t)(n * 3 + c)) * IMGW * IMGW;
        float v00 = (vy0 && vx0) ? __ldg(base + jj0 * IMGW + ii0) : 0.f;
        float v01 = (vy0 && vx1) ? __ldg(base + jj0 * IMGW + ii1) : 0.f;
        float v10 = (vy1 && vx0) ? __ldg(base + jj1 * IMGW + ii0) : 0.f;
        float v11 = (vy1 && vx1) ? __ldg(base + jj1 * IMGW + ii1) : 0.f;
        float val = v00 * w00 + v01 * w01 + v10 * w10 + v11 * w11;
        out[96 + (((size_t)(n * 3 + c)) << 20) + (size_t)pxg * TGRID + pyg] = val;
    }
}

extern "C" void kernel_launch(void* const* d_in, const int* in_sizes, int n_in,
                              void* d_out, int out_size) {
    const float* x   = (const float*)d_in[0];
    const float* uv  = (const float*)d_in[1];
    const float* xyz = (const float*)d_in[2];
    const float* w1  = (const float*)d_in[3];
    const float* b1  = (const float*)d_in[4];
    const float* w2  = (const float*)d_in[5];
    const float* b2  = (const float*)d_in[6];
    const float* fw1 = (const float*)d_in[7];
    const float* fb1 = (const float*)d_in[8];
    const float* fw2 = (const float*)d_in[9];
    const float* fb2 = (const float*)d_in[10];
    float* out = (float*)d_out;

    // Side stream + events: created once (host objects only; GPU work per call
    // is identical). Fork/join via events is graph-capture-legal and creates
    // parallel branches in the captured graph.
    static cudaStream_t s_side = nullptr;
    static cudaEvent_t  s_fork = nullptr, s_join = nullptr;
    if (!s_side) {
        cudaStreamCreateWithFlags(&s_side, cudaStreamNonBlocking);
        cudaEventCreateWithFlags(&s_fork, cudaEventDisableTiming);
        cudaEventCreateWithFlags(&s_join, cudaEventDisableTiming);
    }

    // fork: fill runs concurrently with the conv chain
    cudaEventRecord(s_fork, 0);
    cudaStreamWaitEvent(s_side, s_fork, 0);
    dim3 fg(64, 24);
    fill_kernel<<<fg, 256, 0, s_side>>>(x, out + 96);
    cudaEventRecord(s_join, s_side);

    // main chain
    conv1_kernel<<<C1_BLOCKS, 256>>>(x, w1, b1);
    conv2_kernel<<<C2_BLOCKS, 256>>>(w2, b2);
    fc1_kernel<<<32, 256>>>(fw1, fb1);

    // join: scatter needs both fc1 (chain) and fill (side) complete
    cudaStreamWaitEvent(0, s_join, 0);
    scatter_kernel<<<32, 256>>>(x, uv, xyz, fw2, fb2, out);
}

// round 9
// speedup vs baseline: 1.2675x; 1.1985x over previous
#include <cuda_runtime.h>
#include <math.h>

#define NB 8
#define IMGW 120
#define TGRID 1024
#define PPTS 1024

#define C1_THREADS (NB * 2 * 57 * 57)
#define C1_BLOCKS ((C1_THREADS + 255) / 256)     // 204
#define C2_THREADS (NB * 10 * 26 * 26)
#define C2_BLOCKS ((C2_THREADS + 255) / 256)     // 212

#define H1_STRIDE 58

// scratch (no allocations allowed)
__device__ float g_h1[NB * 8 * 57 * H1_STRIDE];
__device__ float g_h2[NB * 10 * 26 * 26];
__device__ float g_z[NB * 32];

// ---------------- conv1 (3->8, 7x7, pool, relu) ----------------
__global__ __launch_bounds__(256) void conv1_kernel(const float* __restrict__ x,
                                                    const float* __restrict__ w,
                                                    const float* __restrict__ b) {
    __shared__ float ws[8 * 3 * 49];
    __shared__ float bs[8];
    for (int i = threadIdx.x; i < 8 * 3 * 49; i += 256) ws[i] = w[i];
    if (threadIdx.x < 8) bs[threadIdx.x] = b[threadIdx.x];
    __syncthreads();

    int idx = blockIdx.x * 256 + threadIdx.x;
    if (idx >= C1_THREADS) return;
    int px  = idx % 57;
    int py  = (idx / 57) % 57;
    int ocg = (idx / 3249) & 1;
    int n   = idx / 6498;

    float acc[4][4];
#pragma unroll
    for (int oc = 0; oc < 4; oc++)
        acc[oc][0] = acc[oc][1] = acc[oc][2] = acc[oc][3] = 0.f;

    const float* xb = x + (size_t)n * 3 * IMGW * IMGW;
    for (int ic = 0; ic < 3; ic++) {
        const float* xc = xb + ic * IMGW * IMGW + (2 * py) * IMGW + 2 * px;
#pragma unroll
        for (int wy = 0; wy < 8; wy++) {
            const float2* row = reinterpret_cast<const float2*>(xc + wy * IMGW);
            float v[8];
#pragma unroll
            for (int j = 0; j < 4; j++) {
                float2 t = __ldg(row + j);
                v[2 * j] = t.x; v[2 * j + 1] = t.y;
            }
#pragma unroll
            for (int oc = 0; oc < 4; oc++) {
                const float* wr = ws + ((ocg * 4 + oc) * 3 + ic) * 49;
                if (wy < 7) {
#pragma unroll
                    for (int kx = 0; kx < 7; kx++) {
                        float wv = wr[wy * 7 + kx];
                        acc[oc][0] = fmaf(wv, v[kx], acc[oc][0]);
                        acc[oc][1] = fmaf(wv, v[kx + 1], acc[oc][1]);
                    }
                }
                if (wy >= 1) {
#pragma unroll
                    for (int kx = 0; kx < 7; kx++) {
                        float wv = wr[(wy - 1) * 7 + kx];
                        acc[oc][2] = fmaf(wv, v[kx], acc[oc][2]);
                        acc[oc][3] = fmaf(wv, v[kx + 1], acc[oc][3]);
                    }
                }
            }
        }
    }
#pragma unroll
    for (int oc = 0; oc < 4; oc++) {
        int woc = ocg * 4 + oc;
        float m = fmaxf(fmaxf(acc[oc][0], acc[oc][1]), fmaxf(acc[oc][2], acc[oc][3]));
        g_h1[((n * 8 + woc) * 57 + py) * H1_STRIDE + px] = fmaxf(m + bs[woc], 0.f);
    }
}

// ---------------- conv2 (8->10, 5x5, pool, relu) ----------------
__global__ __launch_bounds__(256) void conv2_kernel(const float* __restrict__ w,
                                                    const float* __restrict__ b) {
    __shared__ float ws[10 * 8 * 25];
    __shared__ float bs[10];
    for (int i = threadIdx.x; i < 2000; i += 256) ws[i] = w[i];
    if (threadIdx.x < 10) bs[threadIdx.x] = b[threadIdx.x];
    __syncthreads();

    int idx = blockIdx.x * 256 + threadIdx.x;
    if (idx >= C2_THREADS) return;
    int px = idx % 26;
    int py = (idx / 26) % 26;
    int oc = (idx / 676) % 10;
    int n  = idx / 6760;

    float a0 = 0.f, a1 = 0.f, a2 = 0.f, a3 = 0.f;
    for (int ic = 0; ic < 8; ic++) {
        const float* xc = g_h1 + ((n * 8 + ic) * 57 + 2 * py) * H1_STRIDE + 2 * px;
        const float* wr = ws + (oc * 8 + ic) * 25;
#pragma unroll
        for (int wy = 0; wy < 6; wy++) {
            const float2* row = reinterpret_cast<const float2*>(xc + wy * H1_STRIDE);
            float v[6];
#pragma unroll
            for (int j = 0; j < 3; j++) {
                float2 t = row[j];
                v[2 * j] = t.x; v[2 * j + 1] = t.y;
            }
            if (wy < 5) {
#pragma unroll
                for (int kx = 0; kx < 5; kx++) {
                    float wv = wr[wy * 5 + kx];
                    a0 = fmaf(wv, v[kx], a0);
                    a1 = fmaf(wv, v[kx + 1], a1);
                }
            }
            if (wy >= 1) {
#pragma unroll
                for (int kx = 0; kx < 5; kx++) {
                    float wv = wr[(wy - 1) * 5 + kx];
                    a2 = fmaf(wv, v[kx], a2);
                    a3 = fmaf(wv, v[kx + 1], a3);
                }
            }
        }
    }
    float m = fmaxf(fmaxf(a0, a1), fmaxf(a2, a3));
    g_h2[idx] = fmaxf(m + bs[oc], 0.f);
}

// ---------------- fc1: BLOCK per (n,j) — 256 blocks, high MLP ----------------
__global__ __launch_bounds__(256) void fc1_kernel(const float* __restrict__ fw1,
                                                  const float* __restrict__ fb1) {
    __shared__ float red[8];
    const int n = blockIdx.x >> 5;
    const int j = blockIdx.x & 31;
    const int t = threadIdx.x;

    const float4* wrow = reinterpret_cast<const float4*>(fw1 + j * 6760);
    const float4* hrow = reinterpret_cast<const float4*>(g_h2 + n * 6760);
    float s = 0.f;
    // 1690 float4 = 6*256 + 154
#pragma unroll 7
    for (int k4 = t; k4 < 1690; k4 += 256) {
        float4 wv = __ldg(wrow + k4);
        float4 hv = hrow[k4];
        s = fmaf(wv.x, hv.x, s);
        s = fmaf(wv.y, hv.y, s);
        s = fmaf(wv.z, hv.z, s);
        s = fmaf(wv.w, hv.w, s);
    }
#pragma unroll
    for (int off = 16; off; off >>= 1) s += __shfl_down_sync(0xffffffffu, s, off);
    if ((t & 31) == 0) red[t >> 5] = s;
    __syncthreads();
    if (t < 8) {
        float v = red[t];
#pragma unroll
        for (int off = 4; off; off >>= 1) v += __shfl_down_sync(0xffu, v, off, 8);
        if (t == 0) g_z[n * 32 + j] = fmaxf(v + fb1[j], 0.f);
    }
}

// ---------------- fill: background constants, 64 blocks x 24 planes ----------
__global__ __launch_bounds__(256) void fill_kernel(const float* __restrict__ x,
                                                   float* __restrict__ out96) {
    int plane = blockIdx.y;           // 0..23
    const float* xb = x + (size_t)plane * IMGW * IMGW;
    float cst = 0.25f * (__ldg(xb + 59 * IMGW + 59) + __ldg(xb + 59 * IMGW + 60) +
                         __ldg(xb + 60 * IMGW + 59) + __ldg(xb + 60 * IMGW + 60));
    float4 v = make_float4(cst, cst, cst, cst);
    float4* o = reinterpret_cast<float4*>(out96 + (size_t)plane * TGRID * TGRID);
    int stride = gridDim.x * 256;
#pragma unroll 4
    for (int i = blockIdx.x * 256 + threadIdx.x; i < (TGRID * TGRID / 4); i += stride)
        o[i] = v;
}

// ---------------- scatter: fc2 + Rodrigues + bilinear, 32 blocks -------------
__global__ __launch_bounds__(256) void scatter_kernel(const float* __restrict__ x,
                                                      const float* __restrict__ uv,
                                                      const float* __restrict__ xyz,
                                                      const float* __restrict__ fw2,
                                                      const float* __restrict__ fb2,
                                                      float* __restrict__ out) {
    int b = blockIdx.x;
    int n = b >> 2;
    int q = b & 3;
    int t = threadIdx.x;

    __shared__ float z[32];
    __shared__ float theta[7];
    __shared__ float Tm[12];

    if (t < 32) z[t] = g_z[n * 32 + t];
    __syncthreads();
    if (t < 7) {
        float a = fb2[t];
#pragma unroll
        for (int jj = 0; jj < 32; jj++) a = fmaf(fw2[t * 32 + jj], z[jj], a);
        theta[t] = a;
    }
    __syncthreads();
    if (t == 0) {
        float s0 = fabsf(theta[0]);
        float vx = theta[1], vy = theta[2], vz = theta[3];
        float ang = sqrtf(vx * vx + vy * vy + vz * vz + 1e-8f);
        float kx = vx / ang, ky = vy / ang, kz = vz / ang;
        float sn = sinf(ang);
        float cc = 1.0f - cosf(ang);
        float K[9] = {0.f, -kz, ky,  kz, 0.f, -kx,  -ky, kx, 0.f};
#pragma unroll
        for (int i = 0; i < 3; i++) {
#pragma unroll
            for (int jj = 0; jj < 3; jj++) {
                float kk = 0.f;
#pragma unroll
                for (int m = 0; m < 3; m++) kk += K[i * 3 + m] * K[m * 3 + jj];
                Tm[i * 4 + jj] = (((i == jj) ? 1.f : 0.f) + sn * K[i * 3 + jj] + cc * kk) * s0;
            }
            Tm[i * 4 + 3] = theta[4 + i];
        }
    }
    __syncthreads();

    if (q == 0 && t < 12) out[n * 12 + t] = Tm[t];

    int p = q * 256 + t;
    float X = xyz[p * 3 + 0], Y = xyz[p * 3 + 1], Z = xyz[p * 3 + 2];
    float p0 = Tm[0] * X + Tm[1] * Y + Tm[2] * Z + Tm[3];
    float p1 = Tm[4] * X + Tm[5] * Y + Tm[6] * Z + Tm[7];

    float xs = p0 / (float)IMGW * 2.0f - 1.0f;
    float ys = -(p1 / (float)IMGW * 2.0f - 1.0f);

    float ix = ((xs + 1.0f) * (float)IMGW - 1.0f) * 0.5f;
    float iy = ((ys + 1.0f) * (float)IMGW - 1.0f) * 0.5f;

    float ix0f = floorf(ix), iy0f = floorf(iy);
    float ix1f = ix0f + 1.0f, iy1f = iy0f + 1.0f;
    float wx1 = ix - ix0f, wx0 = 1.0f - wx1;
    float wy1 = iy - iy0f, wy0 = 1.0f - wy1;

    bool vx0 = (ix0f >= 0.f) && (ix0f < (float)IMGW);
    bool vx1 = (ix1f >= 0.f) && (ix1f < (float)IMGW);
    bool vy0 = (iy0f >= 0.f) && (iy0f < (float)IMGW);
    bool vy1 = (iy1f >= 0.f) && (iy1f < (float)IMGW);

    int ii0 = (int)fminf(fmaxf(ix0f, 0.f), (float)(IMGW - 1));
    int ii1 = (int)fminf(fmaxf(ix1f, 0.f), (float)(IMGW - 1));
    int jj0 = (int)fminf(fmaxf(iy0f, 0.f), (float)(IMGW - 1));
    int jj1 = (int)fminf(fmaxf(iy1f, 0.f), (float)(IMGW - 1));

    int pxg = (int)floorf(uv[p * 2 + 0] * (float)TGRID);
    int pyg = (int)floorf(uv[p * 2 + 1] * (float)TGRID);
    if (pxg < 0 || pxg >= TGRID || pyg < 0 || pyg >= TGRID) return;

    float w00 = wy0 * wx0, w01 = wy0 * wx1, w10 = wy1 * wx0, w11 = wy1 * wx1;

#pragma unroll
    for (int c = 0; c < 3; c++) {
        const float* base = x + ((size_t)(n * 3 + c)) * IMGW * IMGW;
        float v00 = (vy0 && vx0) ? __ldg(base + jj0 * IMGW + ii0) : 0.f;
        float v01 = (vy0 && vx1) ? __ldg(base + jj0 * IMGW + ii1) : 0.f;
        float v10 = (vy1 && vx0) ? __ldg(base + jj1 * IMGW + ii0) : 0.f;
        float v11 = (vy1 && vx1) ? __ldg(base + jj1 * IMGW + ii1) : 0.f;
        float val = v00 * w00 + v01 * w01 + v10 * w10 + v11 * w11;
        out[96 + (((size_t)(n * 3 + c)) << 20) + (size_t)pxg * TGRID + pyg] = val;
    }
}

extern "C" void kernel_launch(void* const* d_in, const int* in_sizes, int n_in,
                              void* d_out, int out_size) {
    const float* x   = (const float*)d_in[0];
    const float* uv  = (const float*)d_in[1];
    const float* xyz = (const float*)d_in[2];
    const float* w1  = (const float*)d_in[3];
    const float* b1  = (const float*)d_in[4];
    const float* w2  = (const float*)d_in[5];
    const float* b2  = (const float*)d_in[6];
    const float* fw1 = (const float*)d_in[7];
    const float* fb1 = (const float*)d_in[8];
    const float* fw2 = (const float*)d_in[9];
    const float* fb2 = (const float*)d_in[10];
    float* out = (float*)d_out;

    static cudaStream_t s_side = nullptr;
    static cudaEvent_t  s_fork = nullptr, s_join = nullptr;
    if (!s_side) {
        cudaStreamCreateWithFlags(&s_side, cudaStreamNonBlocking);
        cudaEventCreateWithFlags(&s_fork, cudaEventDisableTiming);
        cudaEventCreateWithFlags(&s_join, cudaEventDisableTiming);
    }

    // fork: fill runs concurrently with the conv chain
    cudaEventRecord(s_fork, 0);
    cudaStreamWaitEvent(s_side, s_fork, 0);
    dim3 fg(64, 24);
    fill_kernel<<<fg, 256, 0, s_side>>>(x, out + 96);
    cudaEventRecord(s_join, s_side);

    // main chain
    conv1_kernel<<<C1_BLOCKS, 256>>>(x, w1, b1);
    conv2_kernel<<<C2_BLOCKS, 256>>>(w2, b2);
    fc1_kernel<<<256, 256>>>(fw1, fb1);

    // join: scatter needs both fc1 (chain) and fill (side) complete
    cudaStreamWaitEvent(0, s_join, 0);
    scatter_kernel<<<32, 256>>>(x, uv, xyz, fw2, fb2, out);
}

// round 10
// speedup vs baseline: 1.4779x; 1.1659x over previous
#include <cuda_runtime.h>
#include <math.h>

#define NB 8
#define IMGW 120
#define TGRID 1024
#define PPTS 1024

#define C1_THREADS (NB * 2 * 57 * 57)
#define C1_BLOCKS ((C1_THREADS + 255) / 256)     // 204
#define C2_THREADS (NB * 10 * 26 * 26)
#define C2_BLOCKS ((C2_THREADS + 255) / 256)     // 212
#define FC1_BLOCKS 256

#define FILL_A (11 * 64)    // planes 0-10
#define FILL_B (8 * 64)     // planes 11-18
#define FILL_C (5 * 64)     // planes 19-23

#define H1_STRIDE 58

// scratch (no allocations allowed)
__device__ float g_h1[NB * 8 * 57 * H1_STRIDE];
__device__ float g_h2[NB * 10 * 26 * 26];
__device__ float g_z[NB * 32];

__device__ __forceinline__ void fill_planes(const float* __restrict__ x,
                                            float* __restrict__ out96,
                                            int fblk, int plane_base) {
    int plane = plane_base + (fblk >> 6);
    if (plane >= 24) return;
    int b = fblk & 63;
    const float* xb = x + (size_t)plane * IMGW * IMGW;
    float cst = 0.25f * (__ldg(xb + 59 * IMGW + 59) + __ldg(xb + 59 * IMGW + 60) +
                         __ldg(xb + 60 * IMGW + 59) + __ldg(xb + 60 * IMGW + 60));
    float4 v = make_float4(cst, cst, cst, cst);
    float4* o = reinterpret_cast<float4*>(out96 + (size_t)plane * TGRID * TGRID);
    const int stride = 64 * 256;
#pragma unroll 4
    for (int i = b * 256 + threadIdx.x; i < (TGRID * TGRID / 4); i += stride)
        o[i] = v;
}

// ---------------- kernel A: conv1 || fill planes 0-10 ----------------
__global__ __launch_bounds__(256) void kernelA(const float* __restrict__ x,
                                               const float* __restrict__ w,
                                               const float* __restrict__ b,
                                               float* __restrict__ out96) {
    if (blockIdx.x >= C1_BLOCKS) {
        fill_planes(x, out96, blockIdx.x - C1_BLOCKS, 0);
        return;
    }

    __shared__ float ws[8 * 3 * 49];
    __shared__ float bs[8];
    for (int i = threadIdx.x; i < 8 * 3 * 49; i += 256) ws[i] = w[i];
    if (threadIdx.x < 8) bs[threadIdx.x] = b[threadIdx.x];
    __syncthreads();

    int idx = blockIdx.x * 256 + threadIdx.x;
    if (idx >= C1_THREADS) return;
    int px  = idx % 57;
    int py  = (idx / 57) % 57;
    int ocg = (idx / 3249) & 1;
    int n   = idx / 6498;

    float acc[4][4];
#pragma unroll
    for (int oc = 0; oc < 4; oc++)
        acc[oc][0] = acc[oc][1] = acc[oc][2] = acc[oc][3] = 0.f;

    const float* xb = x + (size_t)n * 3 * IMGW * IMGW;
    for (int ic = 0; ic < 3; ic++) {
        const float* xc = xb + ic * IMGW * IMGW + (2 * py) * IMGW + 2 * px;
#pragma unroll
        for (int wy = 0; wy < 8; wy++) {
            const float2* row = reinterpret_cast<const float2*>(xc + wy * IMGW);
            float v[8];
#pragma unroll
            for (int j = 0; j < 4; j++) {
                float2 t = __ldg(row + j);
                v[2 * j] = t.x; v[2 * j + 1] = t.y;
            }
#pragma unroll
            for (int oc = 0; oc < 4; oc++) {
                const float* wr = ws + ((ocg * 4 + oc) * 3 + ic) * 49;
                if (wy < 7) {
#pragma unroll
                    for (int kx = 0; kx < 7; kx++) {
                        float wv = wr[wy * 7 + kx];
                        acc[oc][0] = fmaf(wv, v[kx], acc[oc][0]);
                        acc[oc][1] = fmaf(wv, v[kx + 1], acc[oc][1]);
                    }
                }
                if (wy >= 1) {
#pragma unroll
                    for (int kx = 0; kx < 7; kx++) {
                        float wv = wr[(wy - 1) * 7 + kx];
                        acc[oc][2] = fmaf(wv, v[kx], acc[oc][2]);
                        acc[oc][3] = fmaf(wv, v[kx + 1], acc[oc][3]);
                    }
                }
            }
        }
    }
#pragma unroll
    for (int oc = 0; oc < 4; oc++) {
        int woc = ocg * 4 + oc;
        float m = fmaxf(fmaxf(acc[oc][0], acc[oc][1]), fmaxf(acc[oc][2], acc[oc][3]));
        g_h1[((n * 8 + woc) * 57 + py) * H1_STRIDE + px] = fmaxf(m + bs[woc], 0.f);
    }
}

// ---------------- kernel B: conv2 || fill planes 11-18 ----------------
__global__ __launch_bounds__(256) void kernelB(const float* __restrict__ x,
                                               const float* __restrict__ w,
                                               const float* __restrict__ b,
                                               float* __restrict__ out96) {
    if (blockIdx.x >= C2_BLOCKS) {
        fill_planes(x, out96, blockIdx.x - C2_BLOCKS, 11);
        return;
    }

    __shared__ float ws[10 * 8 * 25];
    __shared__ float bs[10];
    for (int i = threadIdx.x; i < 2000; i += 256) ws[i] = w[i];
    if (threadIdx.x < 10) bs[threadIdx.x] = b[threadIdx.x];
    __syncthreads();

    int idx = blockIdx.x * 256 + threadIdx.x;
    if (idx >= C2_THREADS) return;
    int px = idx % 26;
    int py = (idx / 26) % 26;
    int oc = (idx / 676) % 10;
    int n  = idx / 6760;

    float a0 = 0.f, a1 = 0.f, a2 = 0.f, a3 = 0.f;
    for (int ic = 0; ic < 8; ic++) {
        const float* xc = g_h1 + ((n * 8 + ic) * 57 + 2 * py) * H1_STRIDE + 2 * px;
        const float* wr = ws + (oc * 8 + ic) * 25;
#pragma unroll
        for (int wy = 0; wy < 6; wy++) {
            const float2* row = reinterpret_cast<const float2*>(xc + wy * H1_STRIDE);
            float v[6];
#pragma unroll
            for (int j = 0; j < 3; j++) {
                float2 t = row[j];
                v[2 * j] = t.x; v[2 * j + 1] = t.y;
            }
            if (wy < 5) {
#pragma unroll
                for (int kx = 0; kx < 5; kx++) {
                    float wv = wr[wy * 5 + kx];
                    a0 = fmaf(wv, v[kx], a0);
                    a1 = fmaf(wv, v[kx + 1], a1);
                }
            }
            if (wy >= 1) {
#pragma unroll
                for (int kx = 0; kx < 5; kx++) {
                    float wv = wr[(wy - 1) * 5 + kx];
                    a2 = fmaf(wv, v[kx], a2);
                    a3 = fmaf(wv, v[kx + 1], a3);
                }
            }
        }
    }
    float m = fmaxf(fmaxf(a0, a1), fmaxf(a2, a3));
    g_h2[idx] = fmaxf(m + bs[oc], 0.f);
}

// ---------------- kernel C: fc1 block-per-(n,j) || fill planes 19-23 ----------
__global__ __launch_bounds__(256) void kernelC(const float* __restrict__ x,
                                               const float* __restrict__ fw1,
                                               const float* __restrict__ fb1,
                                               float* __restrict__ out96) {
    if (blockIdx.x >= FC1_BLOCKS) {
        fill_planes(x, out96, blockIdx.x - FC1_BLOCKS, 19);
        return;
    }
    __shared__ float red[8];
    const int n = blockIdx.x >> 5;
    const int j = blockIdx.x & 31;
    const int t = threadIdx.x;

    const float4* wrow = reinterpret_cast<const float4*>(fw1 + j * 6760);
    const float4* hrow = reinterpret_cast<const float4*>(g_h2 + n * 6760);
    float s = 0.f;
#pragma unroll 7
    for (int k4 = t; k4 < 1690; k4 += 256) {
        float4 wv = __ldg(wrow + k4);
        float4 hv = hrow[k4];
        s = fmaf(wv.x, hv.x, s);
        s = fmaf(wv.y, hv.y, s);
        s = fmaf(wv.z, hv.z, s);
        s = fmaf(wv.w, hv.w, s);
    }
#pragma unroll
    for (int off = 16; off; off >>= 1) s += __shfl_down_sync(0xffffffffu, s, off);
    if ((t & 31) == 0) red[t >> 5] = s;
    __syncthreads();
    if (t < 8) {
        float v = red[t];
#pragma unroll
        for (int off = 4; off; off >>= 1) v += __shfl_down_sync(0xffu, v, off, 8);
        if (t == 0) g_z[n * 32 + j] = fmaxf(v + fb1[j], 0.f);
    }
}

// ---------------- scatter: fc2 + Rodrigues + bilinear, 32 blocks -------------
__global__ __launch_bounds__(256) void scatter_kernel(const float* __restrict__ x,
                                                      const float* __restrict__ uv,
                                                      const float* __restrict__ xyz,
                                                      const float* __restrict__ fw2,
                                                      const float* __restrict__ fb2,
                                                      float* __restrict__ out) {
    int b = blockIdx.x;
    int n = b >> 2;
    int q = b & 3;
    int t = threadIdx.x;

    __shared__ float z[32];
    __shared__ float theta[7];
    __shared__ float Tm[12];

    if (t < 32) z[t] = g_z[n * 32 + t];
    __syncthreads();
    if (t < 7) {
        float a = fb2[t];
#pragma unroll
        for (int jj = 0; jj < 32; jj++) a = fmaf(fw2[t * 32 + jj], z[jj], a);
        theta[t] = a;
    }
    __syncthreads();
    if (t == 0) {
        float s0 = fabsf(theta[0]);
        float vx = theta[1], vy = theta[2], vz = theta[3];
        float ang = sqrtf(vx * vx + vy * vy + vz * vz + 1e-8f);
        float kx = vx / ang, ky = vy / ang, kz = vz / ang;
        float sn = sinf(ang);
        float cc = 1.0f - cosf(ang);
        float K[9] = {0.f, -kz, ky,  kz, 0.f, -kx,  -ky, kx, 0.f};
#pragma unroll
        for (int i = 0; i < 3; i++) {
#pragma unroll
            for (int jj = 0; jj < 3; jj++) {
                float kk = 0.f;
#pragma unroll
                for (int m = 0; m < 3; m++) kk += K[i * 3 + m] * K[m * 3 + jj];
                Tm[i * 4 + jj] = (((i == jj) ? 1.f : 0.f) + sn * K[i * 3 + jj] + cc * kk) * s0;
            }
            Tm[i * 4 + 3] = theta[4 + i];
        }
    }
    __syncthreads();

    if (q == 0 && t < 12) out[n * 12 + t] = Tm[t];

    int p = q * 256 + t;
    float X = xyz[p * 3 + 0], Y = xyz[p * 3 + 1], Z = xyz[p * 3 + 2];
    float p0 = Tm[0] * X + Tm[1] * Y + Tm[2] * Z + Tm[3];
    float p1 = Tm[4] * X + Tm[5] * Y + Tm[6] * Z + Tm[7];

    float xs = p0 / (float)IMGW * 2.0f - 1.0f;
    float ys = -(p1 / (float)IMGW * 2.0f - 1.0f);

    float ix = ((xs + 1.0f) * (float)IMGW - 1.0f) * 0.5f;
    float iy = ((ys + 1.0f) * (float)IMGW - 1.0f) * 0.5f;

    float ix0f = floorf(ix), iy0f = floorf(iy);
    float ix1f = ix0f + 1.0f, iy1f = iy0f + 1.0f;
    float wx1 = ix - ix0f, wx0 = 1.0f - wx1;
    float wy1 = iy - iy0f, wy0 = 1.0f - wy1;

    bool vx0 = (ix0f >= 0.f) && (ix0f < (float)IMGW);
    bool vx1 = (ix1f >= 0.f) && (ix1f < (float)IMGW);
    bool vy0 = (iy0f >= 0.f) && (iy0f < (float)IMGW);
    bool vy1 = (iy1f >= 0.f) && (iy1f < (float)IMGW);

    int ii0 = (int)fminf(fmaxf(ix0f, 0.f), (float)(IMGW - 1));
    int ii1 = (int)fminf(fmaxf(ix1f, 0.f), (float)(IMGW - 1));
    int jj0 = (int)fminf(fmaxf(iy0f, 0.f), (float)(IMGW - 1));
    int jj1 = (int)fminf(fmaxf(iy1f, 0.f), (float)(IMGW - 1));

    int pxg = (int)floorf(uv[p * 2 + 0] * (float)TGRID);
    int pyg = (int)floorf(uv[p * 2 + 1] * (float)TGRID);
    if (pxg < 0 || pxg >= TGRID || pyg < 0 || pyg >= TGRID) return;

    float w00 = wy0 * wx0, w01 = wy0 * wx1, w10 = wy1 * wx0, w11 = wy1 * wx1;

#pragma unroll
    for (int c = 0; c < 3; c++) {
        const float* base = x + ((size_t)(n * 3 + c)) * IMGW * IMGW;
        float v00 = (vy0 && vx0) ? __ldg(base + jj0 * IMGW + ii0) : 0.f;
        float v01 = (vy0 && vx1) ? __ldg(base + jj0 * IMGW + ii1) : 0.f;
        float v10 = (vy1 && vx0) ? __ldg(base + jj1 * IMGW + ii0) : 0.f;
        float v11 = (vy1 && vx1) ? __ldg(base + jj1 * IMGW + ii1) : 0.f;
        float val = v00 * w00 + v01 * w01 + v10 * w10 + v11 * w11;
        out[96 + (((size_t)(n * 3 + c)) << 20) + (size_t)pxg * TGRID + pyg] = val;
    }
}

extern "C" void kernel_launch(void* const* d_in, const int* in_sizes, int n_in,
                              void* d_out, int out_size) {
    const float* x   = (const float*)d_in[0];
    const float* uv  = (const float*)d_in[1];
    const float* xyz = (const float*)d_in[2];
    const float* w1  = (const float*)d_in[3];
    const float* b1  = (const float*)d_in[4];
    const float* w2  = (const float*)d_in[5];
    const float* b2  = (const float*)d_in[6];
    const float* fw1 = (const float*)d_in[7];
    const float* fb1 = (const float*)d_in[8];
    const float* fw2 = (const float*)d_in[9];
    const float* fb2 = (const float*)d_in[10];
    float* out = (float*)d_out;

    kernelA<<<C1_BLOCKS + FILL_A, 256>>>(x, w1, b1, out + 96);
    kernelB<<<C2_BLOCKS + FILL_B, 256>>>(x, w2, b2, out + 96);
    kernelC<<<FC1_BLOCKS + FILL_C, 256>>>(x, fw1, fb1, out + 96);
    scatter_kernel<<<32, 256>>>(x, uv, xyz, fw2, fb2, out);
}